// round 15
// baseline (speedup 1.0000x reference)
#include <cuda_runtime.h>

#define L      2048
#define BATCH  512
#define NDIM   128

#define TT 64
#define BB 64
#define TS 64
#define US 66
#define CH 64          // staged rows per chunk (64*128*4 = 32 KB)
#define CHS 8          // s-tiles per conv chunk (split-K)
#define NBLK 144       // fused pipeline grid (<=148 SMs -> all co-resident)
#define NGRP 18        // leaf counters; 144 = 18 groups x 8 blocks

typedef unsigned long long u64;

// ---------------- scratch (__device__ globals, allocation-free) ----------------
__device__ __align__(16) float g_S[2][NDIM * NDIM];  // A^(2^k) chain, ping-pong
__device__ __align__(16) float g_R[2][NDIM * NDIM];  // (A^(64*2^k))^T chain
__device__ __align__(16) float g_W[64 * NDIM];       // w_j = (A^T)^j B
__device__ __align__(16) float g_Y[32 * NDIM];       // y_i = A^(64 i) C
__device__ float g_h[L];                             // h_n = B A^n C
__device__ __align__(16) float g_part[4][BATCH * L]; // split-K partials (16 MB)
__device__ unsigned g_leaf[NGRP * 32];               // 1 counter per 128B line
__device__ unsigned g_root = 0;
__device__ unsigned g_gen  = 0;

// ---------------------------------------------------------------------------
// Grid-wide barrier with HIERARCHICAL arrival (fix for round-14 finding:
// 144 single-address atomicAdds serialize ~32cyc each at the L2 atomic ALU
// = ~3us/phase; two levels cut arrivals per address to 8 and 18).
// grp = b % NGRP so co-arriving neighbor SMs hit different L2 lines.
// Leaf reset happens before the root add on the same thread (+fence); group
// members re-arrive only after gen flips, so the reset cannot race.
// Bounded spin + nanosleep fallback: hang-proof under any scheduling.
// ---------------------------------------------------------------------------
__device__ __forceinline__ void gbar()
{
    __syncthreads();
    if (threadIdx.x == 0) {
        __threadfence();
        unsigned g = *(volatile unsigned*)&g_gen;
        unsigned* leaf = &g_leaf[(blockIdx.x % NGRP) * 32];
        bool release = false;
        if (atomicAdd(leaf, 1) == (NBLK / NGRP) - 1) {     // last in group
            *leaf = 0;                                     // pre-release: safe
            __threadfence();
            if (atomicAdd(&g_root, 1) == NGRP - 1) {       // last group
                g_root = 0;
                __threadfence();
                atomicAdd(&g_gen, 1);
                release = true;
            }
        }
        if (!release) {
            unsigned spins = 0;
            while (*(volatile unsigned*)&g_gen == g) {
                if (++spins > (1u << 20)) __nanosleep(64); // hang-proof
            }
        }
        __threadfence();
    }
    __syncthreads();
}

// ---------------------------------------------------------------------------
// 512-thread, 4-way k-split column dot. Cross-phase global reads use __ldcg.
// Must be executed by all 512 threads of the block.
// ---------------------------------------------------------------------------
__device__ __forceinline__ float split_dot(const float* __restrict__ M,
                                           const float* sh, float* tile,
                                           int tid, int col, int part)
{
    float a0 = 0.f, a1 = 0.f, a2 = 0.f, a3 = 0.f;
#pragma unroll
    for (int kk = 0; kk < NDIM; kk += CH) {
        __syncthreads();
        const float4* src = (const float4*)(M + kk * NDIM);
        float4* dst = (float4*)tile;
#pragma unroll
        for (int p = 0; p < (CH * NDIM / 4) / 512; ++p)    // 4 indep float4
            dst[p * 512 + tid] = __ldcg(&src[p * 512 + tid]);
        __syncthreads();
#pragma unroll
        for (int q = 0; q < 16; q += 4) {
            a0 += sh[kk + 4 * (q + 0) + part] * tile[(4 * (q + 0) + part) * NDIM + col];
            a1 += sh[kk + 4 * (q + 1) + part] * tile[(4 * (q + 1) + part) * NDIM + col];
            a2 += sh[kk + 4 * (q + 2) + part] * tile[(4 * (q + 2) + part) * NDIM + col];
            a3 += sh[kk + 4 * (q + 3) + part] * tile[(4 * (q + 3) + part) * NDIM + col];
        }
    }
    return (a0 + a1) + (a2 + a3);
}

// ---------------------------------------------------------------------------
// Fused h-pipeline: ONE launch, 11 grid barriers.
//  W phase k (k=0..5): blocks 0-127 square S_k (k==5 -> R_0^T);
//    blocks 128-143 expand w_{2^k+j} (j = b-128, b-112; <=2 per block).
//  Y phase k (k=0..3): blocks 0-127 square R_k; blocks 128+ expand y.
//  Y phase 4: blocks 0-15 expand y_16..31.
//  Final: blocks 0-31 compute h[64 i + j] = w_j . y_i.
// ---------------------------------------------------------------------------
__global__ __launch_bounds__(512) void hpipe_kernel(const float* __restrict__ Af,
                                                    const float* __restrict__ Bf,
                                                    const float* __restrict__ Cf)
{
    __shared__ float sh[NDIM];
    __shared__ __align__(16) float tile[CH * NDIM];
    __shared__ float comb[3 * NDIM];
    const int tid  = threadIdx.x;
    const int col  = tid & 127;
    const int part = tid >> 7;
    const int b    = blockIdx.x;

    // ---------------- W phases ----------------
#pragma unroll 1
    for (int k = 0; k <= 5; ++k) {
        const int m = 1 << k;
        const float* M = (k == 0) ? Af : g_S[k & 1];
        if (b < 128) {                         // ---- squaring row b ----
            if (part == 0) sh[col] = __ldcg(&M[b * NDIM + col]);
            float partial = split_dot(M, sh, tile, tid, col, part);
            __syncthreads();
            if (part) comb[(part - 1) * NDIM + col] = partial;
            __syncthreads();
            if (part == 0) {
                float acc = partial + comb[col] + comb[NDIM + col] + comb[2 * NDIM + col];
                if (k == 5) g_R[0][col * NDIM + b] = acc;   // R_0 = (A^64)^T
                else        g_S[(k + 1) & 1][b * NDIM + col] = acc;
            }
        } else {                               // ---- expand (<=2 vectors) ----
            if (k == 0 && b == 128) {          // seed g_W[0]=B, g_Y[0]=C
                if (tid < NDIM)      g_W[tid] = Bf[tid];
                else if (tid < 256)  g_Y[tid - NDIM] = Cf[tid - NDIM];
            }
#pragma unroll 1
            for (int e = 0; e < 2; ++e) {
                const int j = (b - 128) + 16 * e;
                if (j < m) {
                    if (part == 0) sh[col] = (k == 0) ? Bf[col]
                                                      : __ldcg(&g_W[j * NDIM + col]);
                    float partial = split_dot(M, sh, tile, tid, col, part);
                    __syncthreads();
                    if (part) comb[(part - 1) * NDIM + col] = partial;
                    __syncthreads();
                    if (part == 0) {
                        float acc = partial + comb[col] + comb[NDIM + col] + comb[2 * NDIM + col];
                        g_W[(m + j) * NDIM + col] = acc;
                    }
                    __syncthreads();           // protect sh before next e
                }
            }
        }
        gbar();
    }

    // ---------------- Y phases ----------------
#pragma unroll 1
    for (int k = 0; k <= 4; ++k) {
        const int m = 1 << k;
        const float* R = g_R[k & 1];
        if (k < 4) {
            if (b < 128) {                     // ---- squaring R row b ----
                if (part == 0) sh[col] = __ldcg(&R[b * NDIM + col]);
                float partial = split_dot(R, sh, tile, tid, col, part);
                __syncthreads();
                if (part) comb[(part - 1) * NDIM + col] = partial;
                __syncthreads();
                if (part == 0) {
                    float acc = partial + comb[col] + comb[NDIM + col] + comb[2 * NDIM + col];
                    g_R[(k + 1) & 1][b * NDIM + col] = acc;
                }
            } else {
                const int j = b - 128;
                if (j < m) {                   // ---- expand y ----
                    if (part == 0) sh[col] = __ldcg(&g_Y[j * NDIM + col]);
                    float partial = split_dot(R, sh, tile, tid, col, part);
                    __syncthreads();
                    if (part) comb[(part - 1) * NDIM + col] = partial;
                    __syncthreads();
                    if (part == 0) {
                        float acc = partial + comb[col] + comb[NDIM + col] + comb[2 * NDIM + col];
                        g_Y[(m + j) * NDIM + col] = acc;
                    }
                }
            }
        } else {                               // k == 4: expansions only
            if (b < 16) {
                const int j = b;
                if (part == 0) sh[col] = __ldcg(&g_Y[j * NDIM + col]);
                float partial = split_dot(R, sh, tile, tid, col, part);
                __syncthreads();
                if (part) comb[(part - 1) * NDIM + col] = partial;
                __syncthreads();
                if (part == 0) {
                    float acc = partial + comb[col] + comb[NDIM + col] + comb[2 * NDIM + col];
                    g_Y[(16 + j) * NDIM + col] = acc;
                }
            }
        }
        gbar();
    }

    // ---------------- hdot: h[64 i + j] = w_j . y_i ----------------
    if (b < 32) {
        if (tid < NDIM) sh[tid] = __ldcg(&g_Y[b * NDIM + tid]);
        __syncthreads();
        const int j = tid >> 3, l = tid & 7;   // 64 j's x 8 lanes
        float p = 0.f;
#pragma unroll
        for (int c = 0; c < 16; ++c)
            p += __ldcg(&g_W[j * NDIM + l + 8 * c]) * sh[l + 8 * c];
        p += __shfl_xor_sync(0xFFFFFFFFu, p, 4);
        p += __shfl_xor_sync(0xFFFFFFFFu, p, 2);
        p += __shfl_xor_sync(0xFFFFFFFFu, p, 1);
        if (l == 0) g_h[b * 64 + j] = p;
    }
}

// ---------------------------------------------------------------------------
// Packed f32x2 helpers
// ---------------------------------------------------------------------------
__device__ __forceinline__ void ffma2(u64& d, u64 a, u64 b)
{
    asm("fma.rn.f32x2 %0, %1, %2, %0;" : "+l"(d) : "l"(a), "l"(b));
}
__device__ __forceinline__ u64 splat2(float x)
{
    u64 r; asm("mov.b64 %0, {%1, %1};" : "=l"(r) : "f"(x)); return r;
}
__device__ __forceinline__ void unpack2(u64 v, float& lo, float& hi)
{
    asm("mov.b64 {%0, %1}, %2;" : "=f"(lo), "=f"(hi) : "l"(v));
}

// ---------------------------------------------------------------------------
// Split-K causal Toeplitz conv (unchanged; at FFMA2 roofline).
// ---------------------------------------------------------------------------
__global__ __launch_bounds__(128) void conv_kernel(const float* __restrict__ u)
{
    __shared__ __align__(16) float Us[TS][US];   // [ss][bb]
    __shared__ float hsArr[132];
    float* hsp = hsArr + 4;

    int bs = blockIdx.x & 7;
    int q  = blockIdx.x >> 3;            // 0..79
    int tileT = 31;
    while (true) { int n = (tileT + 8) >> 3; if (q < n) break; q -= n; --tileT; }
    const int chunk = q;                 // 0..3
    const int t0    = tileT * TT;
    const int b0    = bs * BB;
    const int stLo  = chunk * CHS;
    const int stHi  = min(stLo + CHS - 1, tileT);

    const int tid = threadIdx.x;
    const int tx  = tid & 7;
    const int ty  = tid >> 3;
    const int tt0 = tx * 8;
    const int bb0 = ty * 4;

    u64 acc2[8][2];
#pragma unroll
    for (int r = 0; r < 8; ++r) { acc2[r][0] = 0ull; acc2[r][1] = 0ull; }

    if (tid < 4) hsArr[tid] = 0.0f;      // guards hsp[-4..-1]

    for (int st = stLo; st <= stHi; ++st) {
        const int s0 = st * TS;
        __syncthreads();
        {
            int g = t0 - s0 - 63 + tid;
            hsp[tid] = (g >= 0 && g < L) ? g_h[g] : 0.0f;
        }
#pragma unroll
        for (int p = 0; p < 32; ++p) {
            int f  = p * 128 + tid;
            int bb = f >> 6;
            int ss = f & 63;
            Us[ss][bb] = u[(size_t)(b0 + bb) * L + (s0 + ss)];
        }
        __syncthreads();

        u64 w2[8];
#pragma unroll
        for (int r = 0; r < 8; ++r) w2[r] = splat2(hsp[tt0 + 63 + r]);

#pragma unroll
        for (int ss = 0; ss < TS; ++ss) {
            u64 u01 = *(const u64*)&Us[ss][bb0];
            u64 u23 = *(const u64*)&Us[ss][bb0 + 2];
#pragma unroll
            for (int r = 0; r < 8; ++r) {
                ffma2(acc2[r][0], u01, w2[r]);
                ffma2(acc2[r][1], u23, w2[r]);
            }
            float nw = hsp[tt0 + 62 - ss];
#pragma unroll
            for (int r = 7; r > 0; --r) w2[r] = w2[r - 1];
            w2[0] = splat2(nw);
        }
    }

    float* __restrict__ part = g_part[chunk];
#pragma unroll
    for (int r = 0; r < 8; ++r) {
        const int t = t0 + tt0 + r;
#pragma unroll
        for (int p = 0; p < 2; ++p) {
            float lo, hi;
            unpack2(acc2[r][p], lo, hi);
            const int b = b0 + bb0 + 2 * p;
            part[(size_t)b * L + t]       = lo;
            part[(size_t)(b + 1) * L + t] = hi;
        }
    }
}

// ---------------------------------------------------------------------------
// Reduce: out = f_t * sum_{c<nch(t)} part[c] + D*u.  float4 over t.
// ---------------------------------------------------------------------------
__global__ __launch_bounds__(256) void reduce_kernel(const float* __restrict__ u,
                                                     const float* __restrict__ Dp,
                                                     float* __restrict__ out)
{
    const int idx = blockIdx.x * 256 + threadIdx.x;
    const int e0  = idx * 4;
    const int t   = e0 & (L - 1);
    const int nch = ((t >> 6) + 8) >> 3;

    float4 s = ((const float4*)g_part[0])[idx];
    if (nch > 1) { float4 v = ((const float4*)g_part[1])[idx];
                   s.x += v.x; s.y += v.y; s.z += v.z; s.w += v.w; }
    if (nch > 2) { float4 v = ((const float4*)g_part[2])[idx];
                   s.x += v.x; s.y += v.y; s.z += v.z; s.w += v.w; }
    if (nch > 3) { float4 v = ((const float4*)g_part[3])[idx];
                   s.x += v.x; s.y += v.y; s.z += v.z; s.w += v.w; }

    const float Dv = Dp[0];
    float4 uu = ((const float4*)u)[idx];
    float4 o;
    o.x = ((t == 0) ? 1.0f : 2.0f) * s.x + Dv * uu.x;
    o.y = 2.0f * s.y + Dv * uu.y;
    o.z = 2.0f * s.z + Dv * uu.z;
    o.w = 2.0f * s.w + Dv * uu.w;
    ((float4*)out)[idx] = o;
}

// ---------------------------------------------------------------------------
extern "C" void kernel_launch(void* const* d_in, const int* in_sizes, int n_in,
                              void* d_out, int out_size)
{
    const float* u  = (const float*)d_in[0];  // (512, 2048)
    const float* A  = (const float*)d_in[1];  // (128, 128)
    const float* B  = (const float*)d_in[2];  // (128,)
    const float* Cd = (const float*)d_in[3];  // (128,)
    const float* Dd = (const float*)d_in[4];  // (1,)
    float* out = (float*)d_out;               // (512, 2048)

    hpipe_kernel<<<NBLK, 512>>>(A, B, Cd);    // entire h in ONE launch
    conv_kernel<<<640, 128>>>(u);             // split-K partials
    reduce_kernel<<<(BATCH * L / 4) / 256, 256>>>(u, Dd, out);
}

// round 16
// speedup vs baseline: 1.3071x; 1.3071x over previous
#include <cuda_runtime.h>

#define L      2048
#define BATCH  512
#define NDIM   128

#define TT 64
#define BB 64
#define TS 64
#define US 66
#define CHS 8          // s-tiles per conv chunk (split-K)

typedef unsigned long long u64;

// ---------------- scratch (__device__ globals, allocation-free) ----------------
__device__ __align__(16) float g_S[2][NDIM * NDIM];  // A^(2^k) chain, ping-pong
__device__ __align__(16) float g_R[2][NDIM * NDIM];  // (A^(64*2^k))^T chain
__device__ __align__(16) float g_W[64 * NDIM];       // w_j = (A^T)^j B
__device__ __align__(16) float g_Y[32 * NDIM];       // y_i = A^(64 i) C
__device__ float g_h[L];                             // h_n = B A^n C
__device__ __align__(16) float g_part[4][BATCH * L]; // split-K partials (16 MB)

// ---------------------------------------------------------------------------
// Direct-LDG 4-way-split column dot: result[col] = sum_k sh[k] * M[k*NDIM+col].
// part = tid>>7 covers rows 4q+part (q=0..31). All 32 per-thread loads are
// independent and coalesced across threads (col consecutive) -> structural
// MLP, no smem staging, no fill barriers. L2-hot: every block reads the same
// 64 KB matrix.
// ---------------------------------------------------------------------------
__device__ __forceinline__ float col_dot_direct(const float* __restrict__ M,
                                                const float* sh,
                                                int col, int part)
{
    float a0 = 0.f, a1 = 0.f, a2 = 0.f, a3 = 0.f;
#pragma unroll
    for (int g = 0; g < 4; ++g) {
        float m[8], s[8];
#pragma unroll
        for (int i = 0; i < 8; ++i)
            m[i] = M[(4 * (8 * g + i) + part) * NDIM + col];   // 8 indep LDG
#pragma unroll
        for (int i = 0; i < 8; ++i)
            s[i] = sh[4 * (8 * g + i) + part];
        a0 += s[0] * m[0]; a1 += s[1] * m[1]; a2 += s[2] * m[2]; a3 += s[3] * m[3];
        a0 += s[4] * m[4]; a1 += s[5] * m[5]; a2 += s[6] * m[6]; a3 += s[7] * m[7];
    }
    return (a0 + a1) + (a2 + a3);
}

// Stage k of W phase (k=0..5). 512 threads, 1 row/vector per block.
//   blocks [0,128): squaring S_{k+1} = S_k S_k (k==5: write transposed -> R_0)
//   blocks [128,128+2^k): expand w_{2^k+j} = (A^T)^{2^k} w_j
//   k==0: expand block also seeds g_W[0]=B, g_Y[0]=C.
__global__ __launch_bounds__(512) void stageW_kernel(int k,
                                                     const float* __restrict__ Af,
                                                     const float* __restrict__ Bf,
                                                     const float* __restrict__ Cf)
{
    __shared__ float sh[NDIM];
    __shared__ float comb[3 * NDIM];
    const int tid  = threadIdx.x;
    const int col  = tid & 127;
    const int part = tid >> 7;
    const int m    = 1 << k;
    const float* M = (k == 0) ? Af : g_S[k & 1];
    const bool sq  = blockIdx.x < 128;

    if (sq) {
        if (part == 0) sh[col] = M[blockIdx.x * NDIM + col];
    } else {
        const int j = blockIdx.x - 128;
        if (part == 0) sh[col] = (k == 0) ? Bf[col] : g_W[j * NDIM + col];
        if (k == 0 && part == 1) g_W[col] = Bf[col];
        if (k == 0 && part == 2) g_Y[col] = Cf[col];
    }
    __syncthreads();

    float partial = col_dot_direct(M, sh, col, part);

    if (part) comb[(part - 1) * NDIM + col] = partial;
    __syncthreads();
    if (part == 0) {
        float acc = partial + comb[col] + comb[NDIM + col] + comb[2 * NDIM + col];
        if (sq) {
            if (k == 5) g_R[0][col * NDIM + blockIdx.x] = acc;   // R_0 = (A^64)^T
            else        g_S[(k + 1) & 1][blockIdx.x * NDIM + col] = acc;
        } else {
            g_W[(m + (int)blockIdx.x - 128) * NDIM + col] = acc;
        }
    }
}

// Stage k of Y phase (k=0..4). 512 threads, 1 row/vector per block.
//   k<4 : blocks [0,128) square R_k; blocks [128,128+2^k) expand Y.
//   k==4: blocks [0,16) expand y_{16+b} AND compute h rows; blocks [16,32)
//         compute h rows for i<16 (hdot merged into this launch).
__global__ __launch_bounds__(512) void stageY_kernel(int k)
{
    __shared__ float sh[NDIM];
    __shared__ float comb[3 * NDIM];
    __shared__ float ys[NDIM];
    const int tid  = threadIdx.x;
    const int col  = tid & 127;
    const int part = tid >> 7;
    const int m    = 1 << k;
    const float* R = g_R[k & 1];
    const bool sq  = (k < 4) && (blockIdx.x < 128);
    const int base = (k < 4) ? 128 : 0;
    const bool hdotOnly = (k == 4) && ((int)blockIdx.x >= 16);

    if (!hdotOnly) {
        const int b = (int)blockIdx.x - base;          // expand index (if !sq)
        if (part == 0) sh[col] = sq ? R[blockIdx.x * NDIM + col]
                                    : g_Y[b * NDIM + col];
        __syncthreads();
        float partial = col_dot_direct(R, sh, col, part);
        if (part) comb[(part - 1) * NDIM + col] = partial;
        __syncthreads();
        if (part == 0) {
            float acc = partial + comb[col] + comb[NDIM + col] + comb[2 * NDIM + col];
            if (sq) {
                g_R[(k + 1) & 1][blockIdx.x * NDIM + col] = acc;
            } else {
                g_Y[(m + b) * NDIM + col] = acc;
                if (k == 4) ys[col] = acc;             // for inline hdot
            }
        }
    } else {
        if (tid < NDIM) ys[tid] = g_Y[((int)blockIdx.x - 16) * NDIM + tid];
    }

    if (k == 4) {                                      // ---- inline hdot ----
        __syncthreads();
        const int i = ((int)blockIdx.x < 16) ? 16 + (int)blockIdx.x
                                             : (int)blockIdx.x - 16;
        const int j = tid >> 3, l = tid & 7;           // 64 j's x 8 lanes
        float p = 0.f;
#pragma unroll
        for (int c = 0; c < 16; ++c)
            p += g_W[j * NDIM + l + 8 * c] * ys[l + 8 * c];
        p += __shfl_xor_sync(0xFFFFFFFFu, p, 4);
        p += __shfl_xor_sync(0xFFFFFFFFu, p, 2);
        p += __shfl_xor_sync(0xFFFFFFFFu, p, 1);
        if (l == 0) g_h[i * 64 + j] = p;
    }
}

// ---------------------------------------------------------------------------
// Packed f32x2 helpers
// ---------------------------------------------------------------------------
__device__ __forceinline__ void ffma2(u64& d, u64 a, u64 b)
{
    asm("fma.rn.f32x2 %0, %1, %2, %0;" : "+l"(d) : "l"(a), "l"(b));
}
__device__ __forceinline__ u64 splat2(float x)
{
    u64 r; asm("mov.b64 %0, {%1, %1};" : "=l"(r) : "f"(x)); return r;
}
__device__ __forceinline__ void unpack2(u64 v, float& lo, float& hi)
{
    asm("mov.b64 {%0, %1}, %2;" : "=f"(lo), "=f"(hi) : "l"(v));
}

// ---------------------------------------------------------------------------
// Split-K causal Toeplitz conv (unchanged; at FFMA2 roofline).
// ---------------------------------------------------------------------------
__global__ __launch_bounds__(128) void conv_kernel(const float* __restrict__ u)
{
    __shared__ __align__(16) float Us[TS][US];   // [ss][bb]
    __shared__ float hsArr[132];
    float* hsp = hsArr + 4;

    int bs = blockIdx.x & 7;
    int q  = blockIdx.x >> 3;            // 0..79
    int tileT = 31;
    while (true) { int n = (tileT + 8) >> 3; if (q < n) break; q -= n; --tileT; }
    const int chunk = q;                 // 0..3
    const int t0    = tileT * TT;
    const int b0    = bs * BB;
    const int stLo  = chunk * CHS;
    const int stHi  = min(stLo + CHS - 1, tileT);

    const int tid = threadIdx.x;
    const int tx  = tid & 7;
    const int ty  = tid >> 3;
    const int tt0 = tx * 8;
    const int bb0 = ty * 4;

    u64 acc2[8][2];
#pragma unroll
    for (int r = 0; r < 8; ++r) { acc2[r][0] = 0ull; acc2[r][1] = 0ull; }

    if (tid < 4) hsArr[tid] = 0.0f;      // guards hsp[-4..-1]

    for (int st = stLo; st <= stHi; ++st) {
        const int s0 = st * TS;
        __syncthreads();
        {
            int g = t0 - s0 - 63 + tid;
            hsp[tid] = (g >= 0 && g < L) ? g_h[g] : 0.0f;
        }
#pragma unroll
        for (int p = 0; p < 32; ++p) {
            int f  = p * 128 + tid;
            int bb = f >> 6;
            int ss = f & 63;
            Us[ss][bb] = u[(size_t)(b0 + bb) * L + (s0 + ss)];
        }
        __syncthreads();

        u64 w2[8];
#pragma unroll
        for (int r = 0; r < 8; ++r) w2[r] = splat2(hsp[tt0 + 63 + r]);

#pragma unroll
        for (int ss = 0; ss < TS; ++ss) {
            u64 u01 = *(const u64*)&Us[ss][bb0];
            u64 u23 = *(const u64*)&Us[ss][bb0 + 2];
#pragma unroll
            for (int r = 0; r < 8; ++r) {
                ffma2(acc2[r][0], u01, w2[r]);
                ffma2(acc2[r][1], u23, w2[r]);
            }
            float nw = hsp[tt0 + 62 - ss];
#pragma unroll
            for (int r = 7; r > 0; --r) w2[r] = w2[r - 1];
            w2[0] = splat2(nw);
        }
    }

    float* __restrict__ part = g_part[chunk];
#pragma unroll
    for (int r = 0; r < 8; ++r) {
        const int t = t0 + tt0 + r;
#pragma unroll
        for (int p = 0; p < 2; ++p) {
            float lo, hi;
            unpack2(acc2[r][p], lo, hi);
            const int b = b0 + bb0 + 2 * p;
            part[(size_t)b * L + t]       = lo;
            part[(size_t)(b + 1) * L + t] = hi;
        }
    }
}

// ---------------------------------------------------------------------------
// Reduce: out = f_t * sum_{c<nch(t)} part[c] + D*u.  float4 over t.
// ---------------------------------------------------------------------------
__global__ __launch_bounds__(256) void reduce_kernel(const float* __restrict__ u,
                                                     const float* __restrict__ Dp,
                                                     float* __restrict__ out)
{
    const int idx = blockIdx.x * 256 + threadIdx.x;
    const int e0  = idx * 4;
    const int t   = e0 & (L - 1);
    const int nch = ((t >> 6) + 8) >> 3;

    float4 s = ((const float4*)g_part[0])[idx];
    if (nch > 1) { float4 v = ((const float4*)g_part[1])[idx];
                   s.x += v.x; s.y += v.y; s.z += v.z; s.w += v.w; }
    if (nch > 2) { float4 v = ((const float4*)g_part[2])[idx];
                   s.x += v.x; s.y += v.y; s.z += v.z; s.w += v.w; }
    if (nch > 3) { float4 v = ((const float4*)g_part[3])[idx];
                   s.x += v.x; s.y += v.y; s.z += v.z; s.w += v.w; }

    const float Dv = Dp[0];
    float4 uu = ((const float4*)u)[idx];
    float4 o;
    o.x = ((t == 0) ? 1.0f : 2.0f) * s.x + Dv * uu.x;
    o.y = 2.0f * s.y + Dv * uu.y;
    o.z = 2.0f * s.z + Dv * uu.z;
    o.w = 2.0f * s.w + Dv * uu.w;
    ((float4*)out)[idx] = o;
}

// ---------------------------------------------------------------------------
extern "C" void kernel_launch(void* const* d_in, const int* in_sizes, int n_in,
                              void* d_out, int out_size)
{
    const float* u  = (const float*)d_in[0];  // (512, 2048)
    const float* A  = (const float*)d_in[1];  // (128, 128)
    const float* B  = (const float*)d_in[2];  // (128,)
    const float* Cd = (const float*)d_in[3];  // (128,)
    const float* Dd = (const float*)d_in[4];  // (1,)
    float* out = (float*)d_out;               // (512, 2048)

    for (int k = 0; k <= 5; ++k)
        stageW_kernel<<<128 + (1 << k), 512>>>(k, A, B, Cd);

    for (int k = 0; k <= 4; ++k) {
        int grid = (k < 4) ? 128 + (1 << k) : 32;     // k==4: 16 expand + 16 hdot
        stageY_kernel<<<grid, 512>>>(k);
    }

    conv_kernel<<<640, 128>>>(u);                     // split-K partials
    reduce_kernel<<<(BATCH * L / 4) / 256, 256>>>(u, Dd, out);
}

// round 17
// speedup vs baseline: 1.3075x; 1.0003x over previous
#include <cuda_runtime.h>

#define L      2048
#define BATCH  512
#define NDIM   128

#define TT 64
#define BB 64
#define TS 64
#define US 66
#define CHS 8          // s-tiles per conv chunk (split-K)

typedef unsigned long long u64;

// ---------------- scratch (__device__ globals, allocation-free) ----------------
__device__ __align__(16) float g_S[2][NDIM * NDIM];  // A^(2^k) chain, ping-pong
__device__ __align__(16) float g_R[2][NDIM * NDIM];  // (A^(64*2^k))^T chain
__device__ __align__(16) float g_W[64 * NDIM];       // w_j = (A^T)^j B
__device__ __align__(16) float g_Y[32 * NDIM];       // y_i = A^(64 i) C
__device__ float g_h[L];                             // h_n = B A^n C
__device__ __align__(16) float g_part[4][BATCH * L]; // split-K partials (16 MB)

// ---------------------------------------------------------------------------
// Direct-LDG 4-way-split column dot: result[col] = sum_k sh[k] * M[k*NDIM+col].
// part = tid>>7 covers rows 4q+part (q=0..31). All 32 per-thread loads are
// independent and coalesced across threads. Requires a generous register
// budget so the 8-wide batches stay in flight (see __launch_bounds__(512,1)
// on the callers: 1 block/SM anyway, so regs/thread can go to 128).
// ---------------------------------------------------------------------------
__device__ __forceinline__ float col_dot_direct(const float* __restrict__ M,
                                                const float* sh,
                                                int col, int part)
{
    float a0 = 0.f, a1 = 0.f, a2 = 0.f, a3 = 0.f;
#pragma unroll
    for (int g = 0; g < 4; ++g) {
        float m[8], s[8];
#pragma unroll
        for (int i = 0; i < 8; ++i)
            m[i] = M[(4 * (8 * g + i) + part) * NDIM + col];   // 8 indep LDG
#pragma unroll
        for (int i = 0; i < 8; ++i)
            s[i] = sh[4 * (8 * g + i) + part];
        a0 += s[0] * m[0]; a1 += s[1] * m[1]; a2 += s[2] * m[2]; a3 += s[3] * m[3];
        a0 += s[4] * m[4]; a1 += s[5] * m[5]; a2 += s[6] * m[6]; a3 += s[7] * m[7];
    }
    return (a0 + a1) + (a2 + a3);
}

// Stage k of W phase (k=0..5). 512 threads, 1 row/vector per block.
//   blocks [0,128): squaring S_{k+1} = S_k S_k (k==5: write transposed -> R_0)
//   blocks [128,128+2^k): expand w_{2^k+j} = (A^T)^{2^k} w_j
//   k==0: expand block also seeds g_W[0]=B, g_Y[0]=C.
__global__ __launch_bounds__(512, 1) void stageW_kernel(int k,
                                                        const float* __restrict__ Af,
                                                        const float* __restrict__ Bf,
                                                        const float* __restrict__ Cf)
{
    __shared__ float sh[NDIM];
    __shared__ float comb[3 * NDIM];
    const int tid  = threadIdx.x;
    const int col  = tid & 127;
    const int part = tid >> 7;
    const int m    = 1 << k;
    const float* M = (k == 0) ? Af : g_S[k & 1];
    const bool sq  = blockIdx.x < 128;

    if (sq) {
        if (part == 0) sh[col] = M[blockIdx.x * NDIM + col];
    } else {
        const int j = blockIdx.x - 128;
        if (part == 0) sh[col] = (k == 0) ? Bf[col] : g_W[j * NDIM + col];
        if (k == 0 && part == 1) g_W[col] = Bf[col];
        if (k == 0 && part == 2) g_Y[col] = Cf[col];
    }
    __syncthreads();

    float partial = col_dot_direct(M, sh, col, part);

    if (part) comb[(part - 1) * NDIM + col] = partial;
    __syncthreads();
    if (part == 0) {
        float acc = partial + comb[col] + comb[NDIM + col] + comb[2 * NDIM + col];
        if (sq) {
            if (k == 5) g_R[0][col * NDIM + blockIdx.x] = acc;   // R_0 = (A^64)^T
            else        g_S[(k + 1) & 1][blockIdx.x * NDIM + col] = acc;
        } else {
            g_W[(m + (int)blockIdx.x - 128) * NDIM + col] = acc;
        }
    }
}

// Stage k of Y phase (k=0..4). 512 threads, 1 row/vector per block.
//   k<4 : blocks [0,128) square R_k; blocks [128,128+2^k) expand Y.
//   k==4: blocks [0,16) expand y_{16+b} AND compute h rows; blocks [16,32)
//         compute h rows for i<16 (hdot merged into this launch).
__global__ __launch_bounds__(512, 1) void stageY_kernel(int k)
{
    __shared__ float sh[NDIM];
    __shared__ float comb[3 * NDIM];
    __shared__ float ys[NDIM];
    const int tid  = threadIdx.x;
    const int col  = tid & 127;
    const int part = tid >> 7;
    const int m    = 1 << k;
    const float* R = g_R[k & 1];
    const bool sq  = (k < 4) && (blockIdx.x < 128);
    const int base = (k < 4) ? 128 : 0;
    const bool hdotOnly = (k == 4) && ((int)blockIdx.x >= 16);

    if (!hdotOnly) {
        const int b = (int)blockIdx.x - base;          // expand index (if !sq)
        if (part == 0) sh[col] = sq ? R[blockIdx.x * NDIM + col]
                                    : g_Y[b * NDIM + col];
        __syncthreads();
        float partial = col_dot_direct(R, sh, col, part);
        if (part) comb[(part - 1) * NDIM + col] = partial;
        __syncthreads();
        if (part == 0) {
            float acc = partial + comb[col] + comb[NDIM + col] + comb[2 * NDIM + col];
            if (sq) {
                g_R[(k + 1) & 1][blockIdx.x * NDIM + col] = acc;
            } else {
                g_Y[(m + b) * NDIM + col] = acc;
                if (k == 4) ys[col] = acc;             // for inline hdot
            }
        }
    } else {
        if (tid < NDIM) ys[tid] = g_Y[((int)blockIdx.x - 16) * NDIM + tid];
    }

    if (k == 4) {                                      // ---- inline hdot ----
        __syncthreads();
        const int i = ((int)blockIdx.x < 16) ? 16 + (int)blockIdx.x
                                             : (int)blockIdx.x - 16;
        const int j = tid >> 3, l = tid & 7;           // 64 j's x 8 lanes
        float p = 0.f;
#pragma unroll
        for (int c = 0; c < 16; ++c)
            p += g_W[j * NDIM + l + 8 * c] * ys[l + 8 * c];
        p += __shfl_xor_sync(0xFFFFFFFFu, p, 4);
        p += __shfl_xor_sync(0xFFFFFFFFu, p, 2);
        p += __shfl_xor_sync(0xFFFFFFFFu, p, 1);
        if (l == 0) g_h[i * 64 + j] = p;
    }
}

// ---------------------------------------------------------------------------
// Packed f32x2 helpers
// ---------------------------------------------------------------------------
__device__ __forceinline__ void ffma2(u64& d, u64 a, u64 b)
{
    asm("fma.rn.f32x2 %0, %1, %2, %0;" : "+l"(d) : "l"(a), "l"(b));
}
__device__ __forceinline__ u64 splat2(float x)
{
    u64 r; asm("mov.b64 %0, {%1, %1};" : "=l"(r) : "f"(x)); return r;
}
__device__ __forceinline__ void unpack2(u64 v, float& lo, float& hi)
{
    asm("mov.b64 {%0, %1}, %2;" : "=f"(lo), "=f"(hi) : "l"(v));
}

// ---------------------------------------------------------------------------
// Split-K causal Toeplitz conv (unchanged).
// ---------------------------------------------------------------------------
__global__ __launch_bounds__(128) void conv_kernel(const float* __restrict__ u)
{
    __shared__ __align__(16) float Us[TS][US];   // [ss][bb]
    __shared__ float hsArr[132];
    float* hsp = hsArr + 4;

    int bs = blockIdx.x & 7;
    int q  = blockIdx.x >> 3;            // 0..79
    int tileT = 31;
    while (true) { int n = (tileT + 8) >> 3; if (q < n) break; q -= n; --tileT; }
    const int chunk = q;                 // 0..3
    const int t0    = tileT * TT;
    const int b0    = bs * BB;
    const int stLo  = chunk * CHS;
    const int stHi  = min(stLo + CHS - 1, tileT);

    const int tid = threadIdx.x;
    const int tx  = tid & 7;
    const int ty  = tid >> 3;
    const int tt0 = tx * 8;
    const int bb0 = ty * 4;

    u64 acc2[8][2];
#pragma unroll
    for (int r = 0; r < 8; ++r) { acc2[r][0] = 0ull; acc2[r][1] = 0ull; }

    if (tid < 4) hsArr[tid] = 0.0f;      // guards hsp[-4..-1]

    for (int st = stLo; st <= stHi; ++st) {
        const int s0 = st * TS;
        __syncthreads();
        {
            int g = t0 - s0 - 63 + tid;
            hsp[tid] = (g >= 0 && g < L) ? g_h[g] : 0.0f;
        }
#pragma unroll
        for (int p = 0; p < 32; ++p) {
            int f  = p * 128 + tid;
            int bb = f >> 6;
            int ss = f & 63;
            Us[ss][bb] = u[(size_t)(b0 + bb) * L + (s0 + ss)];
        }
        __syncthreads();

        u64 w2[8];
#pragma unroll
        for (int r = 0; r < 8; ++r) w2[r] = splat2(hsp[tt0 + 63 + r]);

#pragma unroll
        for (int ss = 0; ss < TS; ++ss) {
            u64 u01 = *(const u64*)&Us[ss][bb0];
            u64 u23 = *(const u64*)&Us[ss][bb0 + 2];
#pragma unroll
            for (int r = 0; r < 8; ++r) {
                ffma2(acc2[r][0], u01, w2[r]);
                ffma2(acc2[r][1], u23, w2[r]);
            }
            float nw = hsp[tt0 + 62 - ss];
#pragma unroll
            for (int r = 7; r > 0; --r) w2[r] = w2[r - 1];
            w2[0] = splat2(nw);
        }
    }

    float* __restrict__ part = g_part[chunk];
#pragma unroll
    for (int r = 0; r < 8; ++r) {
        const int t = t0 + tt0 + r;
#pragma unroll
        for (int p = 0; p < 2; ++p) {
            float lo, hi;
            unpack2(acc2[r][p], lo, hi);
            const int b = b0 + bb0 + 2 * p;
            part[(size_t)b * L + t]       = lo;
            part[(size_t)(b + 1) * L + t] = hi;
        }
    }
}

// ---------------------------------------------------------------------------
// Reduce: out = f_t * sum_{c<nch(t)} part[c] + D*u.  float4 over t.
// ---------------------------------------------------------------------------
__global__ __launch_bounds__(256) void reduce_kernel(const float* __restrict__ u,
                                                     const float* __restrict__ Dp,
                                                     float* __restrict__ out)
{
    const int idx = blockIdx.x * 256 + threadIdx.x;
    const int e0  = idx * 4;
    const int t   = e0 & (L - 1);
    const int nch = ((t >> 6) + 8) >> 3;

    float4 s = ((const float4*)g_part[0])[idx];
    if (nch > 1) { float4 v = ((const float4*)g_part[1])[idx];
                   s.x += v.x; s.y += v.y; s.z += v.z; s.w += v.w; }
    if (nch > 2) { float4 v = ((const float4*)g_part[2])[idx];
                   s.x += v.x; s.y += v.y; s.z += v.z; s.w += v.w; }
    if (nch > 3) { float4 v = ((const float4*)g_part[3])[idx];
                   s.x += v.x; s.y += v.y; s.z += v.z; s.w += v.w; }

    const float Dv = Dp[0];
    float4 uu = ((const float4*)u)[idx];
    float4 o;
    o.x = ((t == 0) ? 1.0f : 2.0f) * s.x + Dv * uu.x;
    o.y = 2.0f * s.y + Dv * uu.y;
    o.z = 2.0f * s.z + Dv * uu.z;
    o.w = 2.0f * s.w + Dv * uu.w;
    ((float4*)out)[idx] = o;
}

// ---------------------------------------------------------------------------
extern "C" void kernel_launch(void* const* d_in, const int* in_sizes, int n_in,
                              void* d_out, int out_size)
{
    const float* u  = (const float*)d_in[0];  // (512, 2048)
    const float* A  = (const float*)d_in[1];  // (128, 128)
    const float* B  = (const float*)d_in[2];  // (128,)
    const float* Cd = (const float*)d_in[3];  // (128,)
    const float* Dd = (const float*)d_in[4];  // (1,)
    float* out = (float*)d_out;               // (512, 2048)

    for (int k = 0; k <= 5; ++k)
        stageW_kernel<<<128 + (1 << k), 512>>>(k, A, B, Cd);

    for (int k = 0; k <= 4; ++k) {
        int grid = (k < 4) ? 128 + (1 << k) : 32;     // k==4: 16 expand + 16 hdot
        stageY_kernel<<<grid, 512>>>(k);
    }

    conv_kernel<<<640, 128>>>(u);                     // split-K partials
    reduce_kernel<<<(BATCH * L / 4) / 256, 256>>>(u, Dd, out);
}